// round 15
// baseline (speedup 1.0000x reference)
#include <cuda_runtime.h>

// KAN 3x3 convolution — polynomialized, row-streaming with rotating partials.
// x: (32, 256, 256) f32 in [0,1), base_weight: (3,3), spline_weight: (3,3,8)
// out: (32, 254, 254) f32
//
// Math: for x in [0,1), spline_p(x) + silu(x)*bw_p ==
//   c0 + c1 x + c2 x^2 + c3 x^3 + d1 relu(x-0.2)^3 + d2 relu(x-0.6)^3
// (silu ~ Chebyshev cubic, abs err ~1.3e-4), constants folded to one C*.
//
// Structure: thread owns a 4-col x 8-row output strip, streams 10 input rows
// ONCE with 3 rotating partial rows. 45 coefs + 12 partials register-resident.
//
// Round-15 change: CTA size 256 -> 128 threads (64x2), same per-thread work.
// Grid 256 -> 512 CTAs of 4 warps: placement balance improves from
// {2 CTAs:108 SMs, 1 CTA:40 SMs} (2:1 warp imbalance, idle chip behind fat
// CTAs) to {4:68, 3:80} (4:3). Worst SMSP gets 3 warps instead of 2.

namespace {
constexpr int H  = 256, W  = 256;
constexpr int Ho = 254, Wo = 254;
constexpr int NB = 8;            // GRID_SIZE + SPLINE_ORDER
constexpr int TW = 4;            // output cols per thread
constexpr int TROWS = 8;         // output rows per thread
constexpr int BTX = 64, BTY = 2; // 128 threads; block covers 256 x 16 outputs

// Chebyshev cubic fit of silu on [0,1]
constexpr float Q0 = 0.0001204f;
constexpr float Q1 = 0.496111f;
constexpr float Q2 = 0.270337f;
constexpr float Q3 = -0.035467f;
}

__global__ __launch_bounds__(BTX * BTY, 4)
void kan_conv_kernel(const float* __restrict__ x,
                     const float* __restrict__ bw,
                     const float* __restrict__ sw,
                     float* __restrict__ out)
{
    // ---- per-block fold into shared memory (threads 0..8) ----
    __shared__ float s_coef[45];  // [p*5 + t], t: c1,c2,c3,d1,d2
    __shared__ float s_c0[9];
    const int tid = threadIdx.y * BTX + threadIdx.x;
    if (tid < 9) {
        const int p = tid;
        float s_[6];
#pragma unroll
        for (int k = 0; k < 6; ++k) s_[k] = __ldg(&sw[p * NB + 2 + k]);
        const float bwp = __ldg(&bw[p]);

        const float D0 = (-s_[0] + 3.0f * s_[1] - 3.0f * s_[2] + s_[3]) * (1.0f / 6.0f);
        const float D1 = (-s_[1] + 3.0f * s_[2] - 3.0f * s_[3] + s_[4]) * (1.0f / 6.0f);
        const float D2 = (-s_[2] + 3.0f * s_[3] - 3.0f * s_[4] + s_[5]) * (1.0f / 6.0f);
        const float A  = (s_[0] + 4.0f * s_[1] + s_[2]) * (1.0f / 6.0f);
        const float B  = (s_[2] - s_[0]) * 0.5f;
        const float C  = (s_[0] - 2.0f * s_[1] + s_[2]) * 0.5f;

        s_coef[p * 5 + 0] = 2.5f * B + 2.5f * C + 1.875f * D0 + bwp * Q1;
        s_coef[p * 5 + 1] = 6.25f * C + 9.375f * D0 + bwp * Q2;
        s_coef[p * 5 + 2] = 15.625f * D0 + bwp * Q3;
        s_coef[p * 5 + 3] = 15.625f * (D1 - D0);
        s_coef[p * 5 + 4] = 15.625f * (D2 - D1);
        s_c0[p] = A + 0.5f * B + 0.25f * C + 0.125f * D0 + bwp * Q0;
    }
    __syncthreads();

    // All 45 coefficients register-resident (indexed p = a*3 + b).
    float C1[9], C2[9], C3[9], D1c[9], D2c[9];
#pragma unroll
    for (int p = 0; p < 9; ++p) {
        C1[p]  = s_coef[p * 5 + 0];
        C2[p]  = s_coef[p * 5 + 1];
        C3[p]  = s_coef[p * 5 + 2];
        D1c[p] = s_coef[p * 5 + 3];
        D2c[p] = s_coef[p * 5 + 4];
    }
    float cstar = 0.0f;
#pragma unroll
    for (int q = 0; q < 9; ++q) cstar += s_c0[q];

    const int batch = blockIdx.z;
    const int oc0 = threadIdx.x * TW;                                   // 0..252
    const int or0 = blockIdx.y * (BTY * TROWS) + threadIdx.y * TROWS;   // 0..248
    const float* __restrict__ xb = x + batch * H * W;
    float* __restrict__ ob = out + batch * Ho * Wo;

    const bool fastcols = (oc0 + TW + 2 <= W);

    // Rotating partial rows: pa = output row ir (a=0), pb = ir-1 (a=1),
    // pc = ir-2 (a=2, completes this iteration).
    float pa[TW], pb[TW], pc[TW];
#pragma unroll
    for (int j = 0; j < TW; ++j) { pa[j] = cstar; pb[j] = cstar; pc[j] = cstar; }

#pragma unroll
    for (int t = 0; t < TROWS + 2; ++t) {
        const int ir = min(or0 + t, H - 1);
        const float* __restrict__ xrow = xb + ir * W;

        float px[TW + 2];
        if (fastcols) {
            const float4 v4 = *reinterpret_cast<const float4*>(xrow + oc0);
            const float2 v2 = *reinterpret_cast<const float2*>(xrow + oc0 + 4);
            px[0] = v4.x; px[1] = v4.y; px[2] = v4.z; px[3] = v4.w;
            px[4] = v2.x; px[5] = v2.y;
        } else {
#pragma unroll
            for (int cc = 0; cc < TW + 2; ++cc)
                px[cc] = __ldg(&xrow[min(oc0 + cc, W - 1)]);
        }

        // Compile-time validity after full unroll:
        const bool vA = (t <= TROWS - 1);
        const bool vB = (t >= 1) && (t <= TROWS);
        const bool vC = (t >= 2);

#pragma unroll
        for (int cc = 0; cc < TW + 2; ++cc) {
            const float xv = px[cc];

            const float x2 = xv * xv;
            const float x3 = x2 * xv;
            const float r1 = fmaxf(xv - 0.2f, 0.0f);
            const float r2 = fmaxf(xv - 0.6f, 0.0f);
            const float R1 = (r1 * r1) * r1;
            const float R2 = (r2 * r2) * r2;

#pragma unroll
            for (int b = 0; b < 3; ++b) {
                const int occ = cc - b;
                if (occ < 0 || occ >= TW) continue;
                if (vA) {              // this input row is tap-row a=0 of pa
                    const int p = b;
                    float v = fmaf(xv, C1[p], pa[occ]);
                    v = fmaf(x2, C2[p], v);
                    v = fmaf(x3, C3[p], v);
                    v = fmaf(R1, D1c[p], v);
                    v = fmaf(R2, D2c[p], v);
                    pa[occ] = v;
                }
                if (vB) {              // a=1 of pb
                    const int p = 3 + b;
                    float v = fmaf(xv, C1[p], pb[occ]);
                    v = fmaf(x2, C2[p], v);
                    v = fmaf(x3, C3[p], v);
                    v = fmaf(R1, D1c[p], v);
                    v = fmaf(R2, D2c[p], v);
                    pb[occ] = v;
                }
                if (vC) {              // a=2 of pc -> completes
                    const int p = 6 + b;
                    float v = fmaf(xv, C1[p], pc[occ]);
                    v = fmaf(x2, C2[p], v);
                    v = fmaf(x3, C3[p], v);
                    v = fmaf(R1, D1c[p], v);
                    v = fmaf(R2, D2c[p], v);
                    pc[occ] = v;
                }
            }
        }

        if (vC) {
            const int oh = or0 + t - 2;
            if (oh < Ho) {
                if (oc0 + TW <= Wo) {
                    // oh*Wo + oc0 even (Wo=254, oc0 mult of 4) -> 8B aligned.
                    float* rowp = ob + oh * Wo + oc0;
                    *reinterpret_cast<float2*>(rowp)     = make_float2(pc[0], pc[1]);
                    *reinterpret_cast<float2*>(rowp + 2) = make_float2(pc[2], pc[3]);
                } else {
#pragma unroll
                    for (int j = 0; j < TW; ++j) {
                        const int ow = oc0 + j;
                        if (ow < Wo) ob[oh * Wo + ow] = pc[j];
                    }
                }
            }
        }

        // Rotate (pure register renaming after full unroll).
#pragma unroll
        for (int j = 0; j < TW; ++j) {
            pc[j] = pb[j];
            pb[j] = pa[j];
            pa[j] = cstar;
        }
    }
}

extern "C" void kernel_launch(void* const* d_in, const int* in_sizes, int n_in,
                              void* d_out, int out_size)
{
    const float* x  = (const float*)d_in[0];
    const float* bw = (const float*)d_in[1];
    const float* sw = (const float*)d_in[2];
    float* out = (float*)d_out;

    dim3 block(BTX, BTY);                       // 128 threads
    dim3 grid(1,
              (Ho + BTY * TROWS - 1) / (BTY * TROWS),   // 16
              32);                                      // 512 CTAs total
    kan_conv_kernel<<<grid, block>>>(x, bw, sw, out);
}

// round 16
// speedup vs baseline: 1.0450x; 1.0450x over previous
#include <cuda_runtime.h>

// KAN 3x3 convolution — polynomialized, row-streaming + software pipelining.
// x: (32, 256, 256) f32 in [0,1), base_weight: (3,3), spline_weight: (3,3,8)
// out: (32, 254, 254) f32
//
// Math: for x in [0,1), spline_p(x) + silu(x)*bw_p ==
//   c0 + c1 x + c2 x^2 + c3 x^3 + d1 relu(x-0.2)^3 + d2 relu(x-0.6)^3
// (silu ~ Chebyshev cubic, abs err ~1.3e-4), constants folded to one C*.
//
// Structure: thread owns a 4-col x 8-row strip, streams 10 input rows with 3
// rotating partial rows; 45 coefs + 12 partials register-resident.
//
// Round-16 changes (attack the 87% stall rate seen in R15):
//  (1) SOFTWARE PIPELINE: row t+1 is loaded into nxt[] BEFORE row t is
//      consumed — one full row of compute (~200+ cyc) covers the ~250-cyc
//      L2 load latency that dominated warp stalls.
//  (2) 64-thread CTAs (32x2), grid 1024: ~6.9 CTAs/SM, 7:6 worst-case
//      balance instead of 4:3, same total warps.

namespace {
constexpr int H  = 256, W  = 256;
constexpr int Ho = 254, Wo = 254;
constexpr int NB = 8;            // GRID_SIZE + SPLINE_ORDER
constexpr int TW = 4;            // output cols per thread
constexpr int TROWS = 8;         // output rows per thread
constexpr int BTX = 32, BTY = 2; // 64 threads; block covers 128 x 16 outputs

// Chebyshev cubic fit of silu on [0,1]
constexpr float Q0 = 0.0001204f;
constexpr float Q1 = 0.496111f;
constexpr float Q2 = 0.270337f;
constexpr float Q3 = -0.035467f;
}

__global__ __launch_bounds__(BTX * BTY, 8)
void kan_conv_kernel(const float* __restrict__ x,
                     const float* __restrict__ bw,
                     const float* __restrict__ sw,
                     float* __restrict__ out)
{
    // ---- per-block fold into shared memory (threads 0..8) ----
    __shared__ float s_coef[45];  // [p*5 + t], t: c1,c2,c3,d1,d2
    __shared__ float s_c0[9];
    const int tid = threadIdx.y * BTX + threadIdx.x;
    if (tid < 9) {
        const int p = tid;
        float s_[6];
#pragma unroll
        for (int k = 0; k < 6; ++k) s_[k] = __ldg(&sw[p * NB + 2 + k]);
        const float bwp = __ldg(&bw[p]);

        const float D0 = (-s_[0] + 3.0f * s_[1] - 3.0f * s_[2] + s_[3]) * (1.0f / 6.0f);
        const float D1 = (-s_[1] + 3.0f * s_[2] - 3.0f * s_[3] + s_[4]) * (1.0f / 6.0f);
        const float D2 = (-s_[2] + 3.0f * s_[3] - 3.0f * s_[4] + s_[5]) * (1.0f / 6.0f);
        const float A  = (s_[0] + 4.0f * s_[1] + s_[2]) * (1.0f / 6.0f);
        const float B  = (s_[2] - s_[0]) * 0.5f;
        const float C  = (s_[0] - 2.0f * s_[1] + s_[2]) * 0.5f;

        s_coef[p * 5 + 0] = 2.5f * B + 2.5f * C + 1.875f * D0 + bwp * Q1;
        s_coef[p * 5 + 1] = 6.25f * C + 9.375f * D0 + bwp * Q2;
        s_coef[p * 5 + 2] = 15.625f * D0 + bwp * Q3;
        s_coef[p * 5 + 3] = 15.625f * (D1 - D0);
        s_coef[p * 5 + 4] = 15.625f * (D2 - D1);
        s_c0[p] = A + 0.5f * B + 0.25f * C + 0.125f * D0 + bwp * Q0;
    }
    __syncthreads();

    float C1[9], C2[9], C3[9], D1c[9], D2c[9];
#pragma unroll
    for (int p = 0; p < 9; ++p) {
        C1[p]  = s_coef[p * 5 + 0];
        C2[p]  = s_coef[p * 5 + 1];
        C3[p]  = s_coef[p * 5 + 2];
        D1c[p] = s_coef[p * 5 + 3];
        D2c[p] = s_coef[p * 5 + 4];
    }
    float cstar = 0.0f;
#pragma unroll
    for (int q = 0; q < 9; ++q) cstar += s_c0[q];

    const int batch = blockIdx.z;
    const int oc0 = blockIdx.x * (BTX * TW) + threadIdx.x * TW;         // 0..252
    const int or0 = blockIdx.y * (BTY * TROWS) + threadIdx.y * TROWS;   // 0..248
    const float* __restrict__ xb = x + batch * H * W;
    float* __restrict__ ob = out + batch * Ho * Wo;

    const bool fastcols = (oc0 + TW + 2 <= W);

    // Row loader (vectorized when fully in-row; oc0 mult of 4 -> 16B aligned).
    auto loadrow = [&](int t, float (&px)[TW + 2]) {
        const int ir = min(or0 + t, H - 1);
        const float* __restrict__ xrow = xb + ir * W;
        if (fastcols) {
            const float4 v4 = *reinterpret_cast<const float4*>(xrow + oc0);
            const float2 v2 = *reinterpret_cast<const float2*>(xrow + oc0 + 4);
            px[0] = v4.x; px[1] = v4.y; px[2] = v4.z; px[3] = v4.w;
            px[4] = v2.x; px[5] = v2.y;
        } else {
#pragma unroll
            for (int cc = 0; cc < TW + 2; ++cc)
                px[cc] = __ldg(&xrow[min(oc0 + cc, W - 1)]);
        }
    };

    // Rotating partial rows.
    float pa[TW], pb[TW], pc[TW];
#pragma unroll
    for (int j = 0; j < TW; ++j) { pa[j] = cstar; pb[j] = cstar; pc[j] = cstar; }

    float cur[TW + 2], nxt[TW + 2];
    loadrow(0, cur);

#pragma unroll
    for (int t = 0; t < TROWS + 2; ++t) {
        // ---- prefetch next row before consuming current ----
        if (t < TROWS + 1) loadrow(t + 1, nxt);

        const bool vA = (t <= TROWS - 1);
        const bool vB = (t >= 1) && (t <= TROWS);
        const bool vC = (t >= 2);

#pragma unroll
        for (int cc = 0; cc < TW + 2; ++cc) {
            const float xv = cur[cc];

            const float x2 = xv * xv;
            const float x3 = x2 * xv;
            const float r1 = fmaxf(xv - 0.2f, 0.0f);
            const float r2 = fmaxf(xv - 0.6f, 0.0f);
            const float R1 = (r1 * r1) * r1;
            const float R2 = (r2 * r2) * r2;

#pragma unroll
            for (int b = 0; b < 3; ++b) {
                const int occ = cc - b;
                if (occ < 0 || occ >= TW) continue;
                if (vA) {
                    const int p = b;
                    float v = fmaf(xv, C1[p], pa[occ]);
                    v = fmaf(x2, C2[p], v);
                    v = fmaf(x3, C3[p], v);
                    v = fmaf(R1, D1c[p], v);
                    v = fmaf(R2, D2c[p], v);
                    pa[occ] = v;
                }
                if (vB) {
                    const int p = 3 + b;
                    float v = fmaf(xv, C1[p], pb[occ]);
                    v = fmaf(x2, C2[p], v);
                    v = fmaf(x3, C3[p], v);
                    v = fmaf(R1, D1c[p], v);
                    v = fmaf(R2, D2c[p], v);
                    pb[occ] = v;
                }
                if (vC) {
                    const int p = 6 + b;
                    float v = fmaf(xv, C1[p], pc[occ]);
                    v = fmaf(x2, C2[p], v);
                    v = fmaf(x3, C3[p], v);
                    v = fmaf(R1, D1c[p], v);
                    v = fmaf(R2, D2c[p], v);
                    pc[occ] = v;
                }
            }
        }

        if (vC) {
            const int oh = or0 + t - 2;
            if (oh < Ho) {
                if (oc0 + TW <= Wo) {
                    // oh*Wo + oc0 even (Wo=254, oc0 mult of 4) -> 8B aligned.
                    float* rowp = ob + oh * Wo + oc0;
                    *reinterpret_cast<float2*>(rowp)     = make_float2(pc[0], pc[1]);
                    *reinterpret_cast<float2*>(rowp + 2) = make_float2(pc[2], pc[3]);
                } else {
#pragma unroll
                    for (int j = 0; j < TW; ++j) {
                        const int ow = oc0 + j;
                        if (ow < Wo) ob[oh * Wo + ow] = pc[j];
                    }
                }
            }
        }

        // Rotate partials + advance pipeline (register renames after unroll).
#pragma unroll
        for (int j = 0; j < TW; ++j) {
            pc[j] = pb[j];
            pb[j] = pa[j];
            pa[j] = cstar;
        }
#pragma unroll
        for (int j = 0; j < TW + 2; ++j) cur[j] = nxt[j];
    }
}

extern "C" void kernel_launch(void* const* d_in, const int* in_sizes, int n_in,
                              void* d_out, int out_size)
{
    const float* x  = (const float*)d_in[0];
    const float* bw = (const float*)d_in[1];
    const float* sw = (const float*)d_in[2];
    float* out = (float*)d_out;

    dim3 block(BTX, BTY);                       // 64 threads
    dim3 grid(2,
              (Ho + BTY * TROWS - 1) / (BTY * TROWS),   // 16
              32);                                      // 1024 CTAs total
    kan_conv_kernel<<<grid, block>>>(x, bw, sw, out);
}

// round 17
// speedup vs baseline: 1.0691x; 1.0230x over previous
#include <cuda_runtime.h>

// KAN 3x3 convolution — polynomialized, row-streaming, occupancy-doubled.
// x: (32, 256, 256) f32 in [0,1), base_weight: (3,3), spline_weight: (3,3,8)
// out: (32, 254, 254) f32
//
// Math: for x in [0,1), spline_p(x) + silu(x)*bw_p ==
//   c0 + c1 x + c2 x^2 + c3 x^3 + d1 relu(x-0.2)^3 + d2 relu(x-0.6)^3
// (silu ~ Chebyshev cubic, abs err ~1.3e-4), constants folded to one C*.
//
// Round-17: TW 4 -> 2 (same TROWS=8 streaming structure). Thread count
// doubles to 129k (R16's 64k capped chip occupancy at 21%); insts/output
// unchanged (~52) since the fold is per-block. Live regs ~74 -> fits the
// 85-reg cap of 6 CTAs/SM (24 warps/SM, ~37% occ). Grid 1024 CTAs of 128
// threads ~ 1.15 waves.

namespace {
constexpr int H  = 256, W  = 256;
constexpr int Ho = 254, Wo = 254;
constexpr int NB = 8;            // GRID_SIZE + SPLINE_ORDER
constexpr int TW = 2;            // output cols per thread
constexpr int TROWS = 8;         // output rows per thread
constexpr int BTX = 64, BTY = 2; // 128 threads; block covers 128 x 16 outputs

// Chebyshev cubic fit of silu on [0,1]
constexpr float Q0 = 0.0001204f;
constexpr float Q1 = 0.496111f;
constexpr float Q2 = 0.270337f;
constexpr float Q3 = -0.035467f;
}

__global__ __launch_bounds__(BTX * BTY, 6)
void kan_conv_kernel(const float* __restrict__ x,
                     const float* __restrict__ bw,
                     const float* __restrict__ sw,
                     float* __restrict__ out)
{
    // ---- per-block fold into shared memory (threads 0..8) ----
    __shared__ float s_coef[45];  // [p*5 + t], t: c1,c2,c3,d1,d2
    __shared__ float s_c0[9];
    const int tid = threadIdx.y * BTX + threadIdx.x;
    if (tid < 9) {
        const int p = tid;
        float s_[6];
#pragma unroll
        for (int k = 0; k < 6; ++k) s_[k] = __ldg(&sw[p * NB + 2 + k]);
        const float bwp = __ldg(&bw[p]);

        const float D0 = (-s_[0] + 3.0f * s_[1] - 3.0f * s_[2] + s_[3]) * (1.0f / 6.0f);
        const float D1 = (-s_[1] + 3.0f * s_[2] - 3.0f * s_[3] + s_[4]) * (1.0f / 6.0f);
        const float D2 = (-s_[2] + 3.0f * s_[3] - 3.0f * s_[4] + s_[5]) * (1.0f / 6.0f);
        const float A  = (s_[0] + 4.0f * s_[1] + s_[2]) * (1.0f / 6.0f);
        const float B  = (s_[2] - s_[0]) * 0.5f;
        const float C  = (s_[0] - 2.0f * s_[1] + s_[2]) * 0.5f;

        s_coef[p * 5 + 0] = 2.5f * B + 2.5f * C + 1.875f * D0 + bwp * Q1;
        s_coef[p * 5 + 1] = 6.25f * C + 9.375f * D0 + bwp * Q2;
        s_coef[p * 5 + 2] = 15.625f * D0 + bwp * Q3;
        s_coef[p * 5 + 3] = 15.625f * (D1 - D0);
        s_coef[p * 5 + 4] = 15.625f * (D2 - D1);
        s_c0[p] = A + 0.5f * B + 0.25f * C + 0.125f * D0 + bwp * Q0;
    }
    __syncthreads();

    float C1[9], C2[9], C3[9], D1c[9], D2c[9];
#pragma unroll
    for (int p = 0; p < 9; ++p) {
        C1[p]  = s_coef[p * 5 + 0];
        C2[p]  = s_coef[p * 5 + 1];
        C3[p]  = s_coef[p * 5 + 2];
        D1c[p] = s_coef[p * 5 + 3];
        D2c[p] = s_coef[p * 5 + 4];
    }
    float cstar = 0.0f;
#pragma unroll
    for (int q = 0; q < 9; ++q) cstar += s_c0[q];

    const int batch = blockIdx.z;
    const int oc0 = blockIdx.x * (BTX * TW) + threadIdx.x * TW;         // 0..254
    const int or0 = blockIdx.y * (BTY * TROWS) + threadIdx.y * TROWS;   // 0..248
    const float* __restrict__ xb = x + batch * H * W;
    float* __restrict__ ob = out + batch * Ho * Wo;

    const bool fastcols = (oc0 + TW + 2 <= W);

    // Row loader: 4 pixels = 2x float2 (oc0 even -> 8B aligned).
    auto loadrow = [&](int t, float (&px)[TW + 2]) {
        const int ir = min(or0 + t, H - 1);
        const float* __restrict__ xrow = xb + ir * W;
        if (fastcols) {
            const float2 v0 = *reinterpret_cast<const float2*>(xrow + oc0);
            const float2 v1 = *reinterpret_cast<const float2*>(xrow + oc0 + 2);
            px[0] = v0.x; px[1] = v0.y; px[2] = v1.x; px[3] = v1.y;
        } else {
#pragma unroll
            for (int cc = 0; cc < TW + 2; ++cc)
                px[cc] = __ldg(&xrow[min(oc0 + cc, W - 1)]);
        }
    };

    // Rotating partial rows.
    float pa[TW], pb[TW], pc[TW];
#pragma unroll
    for (int j = 0; j < TW; ++j) { pa[j] = cstar; pb[j] = cstar; pc[j] = cstar; }

    float cur[TW + 2], nxt[TW + 2];
    loadrow(0, cur);

#pragma unroll
    for (int t = 0; t < TROWS + 2; ++t) {
        // ---- prefetch next row before consuming current ----
        if (t < TROWS + 1) loadrow(t + 1, nxt);

        const bool vA = (t <= TROWS - 1);
        const bool vB = (t >= 1) && (t <= TROWS);
        const bool vC = (t >= 2);

#pragma unroll
        for (int cc = 0; cc < TW + 2; ++cc) {
            const float xv = cur[cc];

            const float x2 = xv * xv;
            const float x3 = x2 * xv;
            const float r1 = fmaxf(xv - 0.2f, 0.0f);
            const float r2 = fmaxf(xv - 0.6f, 0.0f);
            const float R1 = (r1 * r1) * r1;
            const float R2 = (r2 * r2) * r2;

#pragma unroll
            for (int b = 0; b < 3; ++b) {
                const int occ = cc - b;
                if (occ < 0 || occ >= TW) continue;
                if (vA) {
                    const int p = b;
                    float v = fmaf(xv, C1[p], pa[occ]);
                    v = fmaf(x2, C2[p], v);
                    v = fmaf(x3, C3[p], v);
                    v = fmaf(R1, D1c[p], v);
                    v = fmaf(R2, D2c[p], v);
                    pa[occ] = v;
                }
                if (vB) {
                    const int p = 3 + b;
                    float v = fmaf(xv, C1[p], pb[occ]);
                    v = fmaf(x2, C2[p], v);
                    v = fmaf(x3, C3[p], v);
                    v = fmaf(R1, D1c[p], v);
                    v = fmaf(R2, D2c[p], v);
                    pb[occ] = v;
                }
                if (vC) {
                    const int p = 6 + b;
                    float v = fmaf(xv, C1[p], pc[occ]);
                    v = fmaf(x2, C2[p], v);
                    v = fmaf(x3, C3[p], v);
                    v = fmaf(R1, D1c[p], v);
                    v = fmaf(R2, D2c[p], v);
                    pc[occ] = v;
                }
            }
        }

        if (vC) {
            const int oh = or0 + t - 2;
            if (oh < Ho) {
                if (oc0 + TW <= Wo) {
                    // oh*Wo + oc0 even (Wo=254, oc0 even) -> 8B aligned.
                    *reinterpret_cast<float2*>(ob + oh * Wo + oc0) =
                        make_float2(pc[0], pc[1]);
                } else {
#pragma unroll
                    for (int j = 0; j < TW; ++j) {
                        const int ow = oc0 + j;
                        if (ow < Wo) ob[oh * Wo + ow] = pc[j];
                    }
                }
            }
        }

        // Rotate partials + advance pipeline (register renames after unroll).
#pragma unroll
        for (int j = 0; j < TW; ++j) {
            pc[j] = pb[j];
            pb[j] = pa[j];
            pa[j] = cstar;
        }
#pragma unroll
        for (int j = 0; j < TW + 2; ++j) cur[j] = nxt[j];
    }
}

extern "C" void kernel_launch(void* const* d_in, const int* in_sizes, int n_in,
                              void* d_out, int out_size)
{
    const float* x  = (const float*)d_in[0];
    const float* bw = (const float*)d_in[1];
    const float* sw = (const float*)d_in[2];
    float* out = (float*)d_out;

    dim3 block(BTX, BTY);                       // 128 threads
    dim3 grid((Wo + BTX * TW - 1) / (BTX * TW),         // 2
              (Ho + BTY * TROWS - 1) / (BTY * TROWS),   // 16
              32);                                      // 1024 CTAs total
    kan_conv_kernel<<<grid, block>>>(x, bw, sw, out);
}